// round 1
// baseline (speedup 1.0000x reference)
#include <cuda_runtime.h>
#include <math.h>

// Problem constants
#define B_  8
#define T_  2048
#define C_  1024
#define H_  1024
#define SCALE_ (1.0f / 32.0f)   // 1/sqrt(1024)

// Scratch (device globals; allocation-free per harness rules)
__device__ float g_Q[(size_t)B_ * T_ * H_];   // 64 MB
__device__ float g_K[(size_t)B_ * T_ * H_];   // 64 MB
__device__ float g_V[(size_t)B_ * T_ * H_];   // 64 MB
__device__ float g_S[(size_t)B_ * T_ * T_];   // 128 MB

// ---------------------------------------------------------------------------
// Projection GEMM (NN):  Cout[M,N] = A[M,K] @ W[K,N]
// M = B*T = 16384, N = H = 1024, K = C = 1024. Tiles 128x128x16, 256 thr.
// ---------------------------------------------------------------------------
__global__ __launch_bounds__(256)
void proj_gemm(const float* __restrict__ A, const float* __restrict__ W,
               float* __restrict__ Cout)
{
    const int M = B_ * T_;
    const int N = H_;
    const int K = C_;

    __shared__ float As[16][128];   // [k][m] (transposed)
    __shared__ float Bs[16][128];   // [k][n]

    const int tid = threadIdx.x;
    const int tx  = tid & 15;   // n-direction, 0..15
    const int ty  = tid >> 4;   // m-direction, 0..15
    const int m0  = blockIdx.y * 128;
    const int n0  = blockIdx.x * 128;

    float acc[8][8];
    #pragma unroll
    for (int i = 0; i < 8; i++)
        #pragma unroll
        for (int j = 0; j < 8; j++) acc[i][j] = 0.0f;

    for (int k0 = 0; k0 < K; k0 += 16) {
        // Load A tile: 128 rows x 16 cols -> As[k][m]
        #pragma unroll
        for (int l = 0; l < 2; l++) {
            int idx = tid + l * 256;           // 0..511
            int row = idx >> 2;                // 0..127
            int col = (idx & 3) << 2;          // 0,4,8,12
            float4 a = *(const float4*)&A[(size_t)(m0 + row) * K + k0 + col];
            As[col + 0][row] = a.x;
            As[col + 1][row] = a.y;
            As[col + 2][row] = a.z;
            As[col + 3][row] = a.w;
        }
        // Load W tile: 16 rows x 128 cols -> Bs[k][n]
        #pragma unroll
        for (int l = 0; l < 2; l++) {
            int idx = tid + l * 256;
            int row = idx >> 5;                // 0..15
            int col = (idx & 31) << 2;         // 0..124
            float4 b = *(const float4*)&W[(size_t)(k0 + row) * N + n0 + col];
            *(float4*)&Bs[row][col] = b;
        }
        __syncthreads();

        #pragma unroll
        for (int kk = 0; kk < 16; kk++) {
            float ra[8], rb[8];
            #pragma unroll
            for (int i = 0; i < 8; i++) ra[i] = As[kk][ty * 8 + i];
            #pragma unroll
            for (int j = 0; j < 8; j++) rb[j] = Bs[kk][tx * 8 + j];
            #pragma unroll
            for (int i = 0; i < 8; i++)
                #pragma unroll
                for (int j = 0; j < 8; j++)
                    acc[i][j] = fmaf(ra[i], rb[j], acc[i][j]);
        }
        __syncthreads();
    }

    #pragma unroll
    for (int i = 0; i < 8; i++) {
        int m = m0 + ty * 8 + i;
        #pragma unroll
        for (int j = 0; j < 8; j += 4) {
            float4 v = make_float4(acc[i][j], acc[i][j+1], acc[i][j+2], acc[i][j+3]);
            *(float4*)&Cout[(size_t)m * N + n0 + tx * 8 + j] = v;
        }
    }
}

// ---------------------------------------------------------------------------
// S = scale * Q @ K^T  (NT GEMM, per batch, lower-triangular blocks only)
// Per batch: M = N = T = 2048, K = H = 1024.
// grid: (kb=16, qb=16, b=8). Blocks with kb > qb skipped (fully masked).
// ---------------------------------------------------------------------------
__global__ __launch_bounds__(256)
void qk_gemm(const float* __restrict__ Q, const float* __restrict__ Kmat,
             float* __restrict__ S)
{
    const int kb = blockIdx.x;
    const int qb = blockIdx.y;
    if (kb > qb) return;   // entirely above causal diagonal — never read
    const int b  = blockIdx.z;

    const float* Qb = Q    + (size_t)b * T_ * H_;
    const float* Kb = Kmat + (size_t)b * T_ * H_;
    float*       Sb = S    + (size_t)b * T_ * T_;

    __shared__ float As[16][128];   // [h][q]
    __shared__ float Bs[16][128];   // [h][k]

    const int tid = threadIdx.x;
    const int tx  = tid & 15;
    const int ty  = tid >> 4;
    const int q0  = qb * 128;
    const int n0  = kb * 128;

    float acc[8][8];
    #pragma unroll
    for (int i = 0; i < 8; i++)
        #pragma unroll
        for (int j = 0; j < 8; j++) acc[i][j] = 0.0f;

    for (int h0 = 0; h0 < H_; h0 += 16) {
        #pragma unroll
        for (int l = 0; l < 2; l++) {
            int idx = tid + l * 256;
            int row = idx >> 2;
            int col = (idx & 3) << 2;
            float4 a = *(const float4*)&Qb[(size_t)(q0 + row) * H_ + h0 + col];
            As[col + 0][row] = a.x;
            As[col + 1][row] = a.y;
            As[col + 2][row] = a.z;
            As[col + 3][row] = a.w;
        }
        #pragma unroll
        for (int l = 0; l < 2; l++) {
            int idx = tid + l * 256;
            int row = idx >> 2;
            int col = (idx & 3) << 2;
            float4 kv = *(const float4*)&Kb[(size_t)(n0 + row) * H_ + h0 + col];
            Bs[col + 0][row] = kv.x;
            Bs[col + 1][row] = kv.y;
            Bs[col + 2][row] = kv.z;
            Bs[col + 3][row] = kv.w;
        }
        __syncthreads();

        #pragma unroll
        for (int kk = 0; kk < 16; kk++) {
            float ra[8], rb[8];
            #pragma unroll
            for (int i = 0; i < 8; i++) ra[i] = As[kk][ty * 8 + i];
            #pragma unroll
            for (int j = 0; j < 8; j++) rb[j] = Bs[kk][tx * 8 + j];
            #pragma unroll
            for (int i = 0; i < 8; i++)
                #pragma unroll
                for (int j = 0; j < 8; j++)
                    acc[i][j] = fmaf(ra[i], rb[j], acc[i][j]);
        }
        __syncthreads();
    }

    #pragma unroll
    for (int i = 0; i < 8; i++) {
        int q = q0 + ty * 8 + i;
        #pragma unroll
        for (int j = 0; j < 8; j += 4) {
            float4 v = make_float4(acc[i][j]   * SCALE_, acc[i][j+1] * SCALE_,
                                   acc[i][j+2] * SCALE_, acc[i][j+3] * SCALE_);
            *(float4*)&Sb[(size_t)q * T_ + n0 + tx * 8 + j] = v;
        }
    }
}

// ---------------------------------------------------------------------------
// Causal row softmax in place on S. One block per (b, q) row.
// Valid length L = q+1; entries [L, T) set to 0 so P@V diagonal blocks work.
// ---------------------------------------------------------------------------
__global__ __launch_bounds__(256)
void softmax_causal(float* __restrict__ S)
{
    const int row = blockIdx.x;       // 0 .. B*T-1
    const int b   = row >> 11;        // / 2048
    const int q   = row & (T_ - 1);
    float* Sr = S + (size_t)b * T_ * T_ + (size_t)q * T_;
    const int L = q + 1;
    const int tid = threadIdx.x;

    __shared__ float red[8];

    // Pass 1: row max over valid region
    float m = -INFINITY;
    for (int k = tid; k < L; k += 256) m = fmaxf(m, Sr[k]);
    #pragma unroll
    for (int o = 16; o > 0; o >>= 1) m = fmaxf(m, __shfl_xor_sync(0xFFFFFFFFu, m, o));
    if ((tid & 31) == 0) red[tid >> 5] = m;
    __syncthreads();
    float m_all = red[0];
    #pragma unroll
    for (int i = 1; i < 8; i++) m_all = fmaxf(m_all, red[i]);
    __syncthreads();

    // Pass 2: unnormalized exp + sum
    float s = 0.0f;
    for (int k = tid; k < L; k += 256) {
        float e = __expf(Sr[k] - m_all);
        Sr[k] = e;
        s += e;
    }
    #pragma unroll
    for (int o = 16; o > 0; o >>= 1) s += __shfl_xor_sync(0xFFFFFFFFu, s, o);
    if ((tid & 31) == 0) red[tid >> 5] = s;
    __syncthreads();
    float s_all = 0.0f;
    #pragma unroll
    for (int i = 0; i < 8; i++) s_all += red[i];
    const float inv = 1.0f / s_all;

    // Pass 3: normalize valid region, zero the masked tail
    for (int k = tid; k < T_; k += 256)
        Sr[k] = (k < L) ? Sr[k] * inv : 0.0f;
}

// ---------------------------------------------------------------------------
// O = P @ V  (NN GEMM per batch). M = T, N = H, K = T but k-loop clipped to
// (qb+1)*128 (everything beyond is exactly zero from the causal softmax).
// grid: (nb=8, qb=16, b=8)
// ---------------------------------------------------------------------------
__global__ __launch_bounds__(256)
void pv_gemm(const float* __restrict__ P, const float* __restrict__ V,
             float* __restrict__ O)
{
    const int nb = blockIdx.x;
    const int qb = blockIdx.y;
    const int b  = blockIdx.z;

    const float* Pb = P + (size_t)b * T_ * T_;
    const float* Vb = V + (size_t)b * T_ * H_;
    float*       Ob = O + (size_t)b * T_ * H_;

    __shared__ float As[16][128];   // [k][q]
    __shared__ float Bs[16][128];   // [k][n]

    const int tid = threadIdx.x;
    const int tx  = tid & 15;
    const int ty  = tid >> 4;
    const int m0  = qb * 128;
    const int n0  = nb * 128;
    const int kend = (qb + 1) * 128;   // causal clip

    float acc[8][8];
    #pragma unroll
    for (int i = 0; i < 8; i++)
        #pragma unroll
        for (int j = 0; j < 8; j++) acc[i][j] = 0.0f;

    for (int k0 = 0; k0 < kend; k0 += 16) {
        #pragma unroll
        for (int l = 0; l < 2; l++) {
            int idx = tid + l * 256;
            int row = idx >> 2;
            int col = (idx & 3) << 2;
            float4 a = *(const float4*)&Pb[(size_t)(m0 + row) * T_ + k0 + col];
            As[col + 0][row] = a.x;
            As[col + 1][row] = a.y;
            As[col + 2][row] = a.z;
            As[col + 3][row] = a.w;
        }
        #pragma unroll
        for (int l = 0; l < 2; l++) {
            int idx = tid + l * 256;
            int row = idx >> 5;
            int col = (idx & 31) << 2;
            float4 v = *(const float4*)&Vb[(size_t)(k0 + row) * H_ + n0 + col];
            *(float4*)&Bs[row][col] = v;
        }
        __syncthreads();

        #pragma unroll
        for (int kk = 0; kk < 16; kk++) {
            float ra[8], rb[8];
            #pragma unroll
            for (int i = 0; i < 8; i++) ra[i] = As[kk][ty * 8 + i];
            #pragma unroll
            for (int j = 0; j < 8; j++) rb[j] = Bs[kk][tx * 8 + j];
            #pragma unroll
            for (int i = 0; i < 8; i++)
                #pragma unroll
                for (int j = 0; j < 8; j++)
                    acc[i][j] = fmaf(ra[i], rb[j], acc[i][j]);
        }
        __syncthreads();
    }

    #pragma unroll
    for (int i = 0; i < 8; i++) {
        int m = m0 + ty * 8 + i;
        #pragma unroll
        for (int j = 0; j < 8; j += 4) {
            float4 v = make_float4(acc[i][j], acc[i][j+1], acc[i][j+2], acc[i][j+3]);
            *(float4*)&Ob[(size_t)m * H_ + n0 + tx * 8 + j] = v;
        }
    }
}

// ---------------------------------------------------------------------------
// Launch
// ---------------------------------------------------------------------------
extern "C" void kernel_launch(void* const* d_in, const int* in_sizes, int n_in,
                              void* d_out, int out_size)
{
    const float* x  = (const float*)d_in[0];   // [B, T, C]
    const float* Wq = (const float*)d_in[1];   // [C, H]
    const float* Wk = (const float*)d_in[2];   // [C, H]
    const float* Wv = (const float*)d_in[3];   // [C, H]
    float* out = (float*)d_out;                // [B, T, H]

    float *qp, *kp, *vp, *sp;
    cudaGetSymbolAddress((void**)&qp, g_Q);
    cudaGetSymbolAddress((void**)&kp, g_K);
    cudaGetSymbolAddress((void**)&vp, g_V);
    cudaGetSymbolAddress((void**)&sp, g_S);

    // Projections: M = B*T = 16384 (128 tiles), N = 1024 (8 tiles)
    dim3 gproj(H_ / 128, (B_ * T_) / 128);
    proj_gemm<<<gproj, 256>>>(x, Wq, qp);
    proj_gemm<<<gproj, 256>>>(x, Wk, kp);
    proj_gemm<<<gproj, 256>>>(x, Wv, vp);

    // Scores: per batch 16x16 blocks of 128x128 (upper-tri blocks early-exit)
    dim3 gqk(T_ / 128, T_ / 128, B_);
    qk_gemm<<<gqk, 256>>>(qp, kp, sp);

    // Causal softmax: one block per row
    softmax_causal<<<B_ * T_, 256>>>(sp);

    // Output: O = P @ V
    dim3 gpv(H_ / 128, T_ / 128, B_);
    pv_gemm<<<gpv, 256>>>(sp, vp, out);
}

// round 3
// speedup vs baseline: 3.0231x; 3.0231x over previous
#include <cuda_runtime.h>
#include <cstdint>
#include <math.h>

#define B_  8
#define T_  2048
#define C_  1024
#define H_  1024
#define SCALE_ (1.0f / 32.0f)   // 1/sqrt(1024)

// ---------------------------------------------------------------------------
// Scratch (device globals)
// ---------------------------------------------------------------------------
__device__ float g_Q [(size_t)B_ * T_ * H_];   // 64 MB
__device__ float g_K [(size_t)B_ * T_ * H_];   // 64 MB
__device__ float g_V [(size_t)B_ * T_ * H_];   // 64 MB
__device__ float g_VT[(size_t)B_ * H_ * T_];   // 64 MB  V^T per batch [H][T]
__device__ float g_S [(size_t)B_ * T_ * T_];   // 128 MB scores
__device__ float g_WT[3][(size_t)H_ * C_];     // 12 MB  W^T [H][C]

// ---------------------------------------------------------------------------
// tf32 helpers (baseline PTX, valid on compute_103)
// ---------------------------------------------------------------------------
__device__ __forceinline__ uint32_t f2tf32(float f) {
    uint32_t r;
    asm("cvt.rna.tf32.f32 %0, %1;" : "=r"(r) : "f"(f));
    return r;
}

__device__ __forceinline__ void mma_tf32(float c[4], const uint32_t a[4],
                                         const uint32_t b[2]) {
    asm volatile(
        "mma.sync.aligned.m16n8k8.row.col.f32.tf32.tf32.f32 "
        "{%0,%1,%2,%3}, {%4,%5,%6,%7}, {%8,%9}, {%0,%1,%2,%3};"
        : "+f"(c[0]), "+f"(c[1]), "+f"(c[2]), "+f"(c[3])
        : "r"(a[0]), "r"(a[1]), "r"(a[2]), "r"(a[3]), "r"(b[0]), "r"(b[1]));
}

// ---------------------------------------------------------------------------
// Shared GEMM core.
// C[128,128] tile += A[128, 32*ntiles] (row-major, lda) @ B[128, 32*ntiles]^T
// (B stored [n][k], ldb). 256 threads = 8 warps in 2(m) x 4(n), warp = 64x32.
// SMEM: A 128x36, B 128x36 words (pad 4) = 36,864 B. Register-staged pipeline.
// ---------------------------------------------------------------------------
#define LDA_S 36

__device__ __forceinline__ void gemm_core(const float* __restrict__ Ag, int lda,
                                          const float* __restrict__ Bg, int ldb,
                                          float* __restrict__ Cg, int ldc,
                                          int ntiles, float scale)
{
    __shared__ uint32_t As[128 * LDA_S];
    __shared__ uint32_t Bs[128 * LDA_S];

    const int tid  = threadIdx.x;
    const int lane = tid & 31;
    const int wid  = tid >> 5;
    const int wm   = wid & 1;        // 0..1
    const int wn   = wid >> 1;       // 0..3
    const int g    = lane >> 2;      // 0..7
    const int t    = lane & 3;       // 0..3

    // Per-thread gmem/smem coordinates for tile loading (4 float4 per array)
    const int lrowA[4] = { (tid + 0*256) >> 3, (tid + 1*256) >> 3,
                           (tid + 2*256) >> 3, (tid + 3*256) >> 3 };
    const int lk4     = (tid & 7) << 2;   // 0,4,...,28 (same for all 4 chunks)

    float acc[4][4][4];
    #pragma unroll
    for (int i = 0; i < 4; i++)
        #pragma unroll
        for (int j = 0; j < 4; j++)
            #pragma unroll
            for (int r = 0; r < 4; r++) acc[i][j][r] = 0.0f;

    uint32_t stA[4][4], stB[4][4];

    // --- load tile s into staging regs ---
    auto ldg_tile = [&](int s) {
        const float* Ab = Ag + s * 32;
        const float* Bb = Bg + s * 32;
        #pragma unroll
        for (int i = 0; i < 4; i++) {
            float4 va = *(const float4*)(Ab + (size_t)lrowA[i] * lda + lk4);
            stA[i][0] = f2tf32(va.x); stA[i][1] = f2tf32(va.y);
            stA[i][2] = f2tf32(va.z); stA[i][3] = f2tf32(va.w);
            float4 vb = *(const float4*)(Bb + (size_t)lrowA[i] * ldb + lk4);
            stB[i][0] = f2tf32(vb.x); stB[i][1] = f2tf32(vb.y);
            stB[i][2] = f2tf32(vb.z); stB[i][3] = f2tf32(vb.w);
        }
    };
    // --- staging regs -> smem ---
    auto sts_tile = [&]() {
        #pragma unroll
        for (int i = 0; i < 4; i++) {
            *(uint4*)&As[lrowA[i] * LDA_S + lk4] =
                make_uint4(stA[i][0], stA[i][1], stA[i][2], stA[i][3]);
            *(uint4*)&Bs[lrowA[i] * LDA_S + lk4] =
                make_uint4(stB[i][0], stB[i][1], stB[i][2], stB[i][3]);
        }
    };

    ldg_tile(0);
    sts_tile();
    __syncthreads();

    const int mwb = wm * 64;   // warp m base
    const int nwb = wn * 32;   // warp n base

    for (int s = 0; s < ntiles; s++) {
        if (s + 1 < ntiles) ldg_tile(s + 1);

        #pragma unroll
        for (int kk = 0; kk < 32; kk += 8) {
            uint32_t ar[4][4];
            #pragma unroll
            for (int mf = 0; mf < 4; mf++) {
                const int rb = mwb + mf * 16;
                ar[mf][0] = As[(rb + g)     * LDA_S + kk + t];
                ar[mf][1] = As[(rb + g + 8) * LDA_S + kk + t];
                ar[mf][2] = As[(rb + g)     * LDA_S + kk + t + 4];
                ar[mf][3] = As[(rb + g + 8) * LDA_S + kk + t + 4];
            }
            uint32_t br[4][2];
            #pragma unroll
            for (int nf = 0; nf < 4; nf++) {
                const int cb = nwb + nf * 8;
                br[nf][0] = Bs[(cb + g) * LDA_S + kk + t];
                br[nf][1] = Bs[(cb + g) * LDA_S + kk + t + 4];
            }
            #pragma unroll
            for (int mf = 0; mf < 4; mf++)
                #pragma unroll
                for (int nf = 0; nf < 4; nf++)
                    mma_tf32(acc[mf][nf], ar[mf], br[nf]);
        }

        __syncthreads();
        if (s + 1 < ntiles) {
            sts_tile();
            __syncthreads();
        }
    }

    // Epilogue: c0,c1 at (row, 2t..2t+1); c2,c3 at (row+8, same cols)
    #pragma unroll
    for (int mf = 0; mf < 4; mf++) {
        const int row = mwb + mf * 16 + g;
        #pragma unroll
        for (int nf = 0; nf < 4; nf++) {
            const int col = nwb + nf * 8 + 2 * t;
            *(float2*)&Cg[(size_t)row * ldc + col] =
                make_float2(acc[mf][nf][0] * scale, acc[mf][nf][1] * scale);
            *(float2*)&Cg[(size_t)(row + 8) * ldc + col] =
                make_float2(acc[mf][nf][2] * scale, acc[mf][nf][3] * scale);
        }
    }
}

// ---------------------------------------------------------------------------
// Projection: out[m][n] = sum_k A[m][k] WT[n][k].  grid (N/128, M/128)
// ---------------------------------------------------------------------------
__global__ __launch_bounds__(256)
void proj_mma(const float* __restrict__ A, const float* __restrict__ WT,
              float* __restrict__ out)
{
    const int n0 = blockIdx.x * 128;
    const size_t m0 = (size_t)blockIdx.y * 128;
    gemm_core(A + m0 * C_, C_, WT + (size_t)n0 * C_, C_,
              out + m0 * H_ + n0, H_, C_ / 32, 1.0f);
}

// ---------------------------------------------------------------------------
// QK^T: S[q][k] = SCALE * sum_h Q[q][h] K[k][h].  grid (16,16,B), causal skip.
// ---------------------------------------------------------------------------
__global__ __launch_bounds__(256)
void qk_mma()
{
    const int kb = blockIdx.x, qb = blockIdx.y;
    if (kb > qb) return;
    const int b = blockIdx.z;
    const size_t q0 = (size_t)qb * 128, n0 = (size_t)kb * 128;
    const float* Qb = g_Q + (size_t)b * T_ * H_ + q0 * H_;
    const float* Kb = g_K + (size_t)b * T_ * H_ + n0 * H_;
    float*       Sb = g_S + (size_t)b * T_ * T_ + q0 * T_ + n0;
    gemm_core(Qb, H_, Kb, H_, Sb, T_, H_ / 32, SCALE_);
}

// ---------------------------------------------------------------------------
// O = P @ V via VT: O[q][h] = sum_t P[q][t] VT[h][t]. grid (8,16,B), k clipped.
// ---------------------------------------------------------------------------
__global__ __launch_bounds__(256)
void pv_mma(float* __restrict__ out)
{
    const int nb = blockIdx.x, qb = blockIdx.y, b = blockIdx.z;
    const size_t q0 = (size_t)qb * 128, n0 = (size_t)nb * 128;
    const float* Pb  = g_S  + (size_t)b * T_ * T_ + q0 * T_;
    const float* VTb = g_VT + (size_t)b * H_ * T_ + n0 * T_;
    float*       Ob  = out  + (size_t)b * T_ * H_ + q0 * H_ + n0;
    gemm_core(Pb, T_, VTb, T_, Ob, H_, (qb + 1) * 4, 1.0f);
}

// ---------------------------------------------------------------------------
// 32x32 tiled transpose: out[c][r] = in[r][c]. grid.z batches.
// ---------------------------------------------------------------------------
__global__ __launch_bounds__(256)
void transpose_k(const float* __restrict__ in, float* __restrict__ out,
                 int rows, int cols)
{
    __shared__ float tile[32][33];
    const int z = blockIdx.z;
    const float* I = in  + (size_t)z * rows * cols;
    float*       O = out + (size_t)z * rows * cols;
    const int r0 = blockIdx.y * 32, c0 = blockIdx.x * 32;
    const int tx = threadIdx.x & 31, ty = threadIdx.x >> 5;
    #pragma unroll
    for (int i = 0; i < 32; i += 8)
        tile[ty + i][tx] = I[(size_t)(r0 + ty + i) * cols + c0 + tx];
    __syncthreads();
    #pragma unroll
    for (int i = 0; i < 32; i += 8)
        O[(size_t)(c0 + ty + i) * rows + r0 + tx] = tile[tx][ty + i];
}

// ---------------------------------------------------------------------------
// Causal row softmax in place on S. Zeroes the tail up to the 128-block bound
// so pv_mma's clipped k-loop reads exact zeros.
// ---------------------------------------------------------------------------
__global__ __launch_bounds__(256)
void softmax_causal(float* __restrict__ S)
{
    const int row = blockIdx.x;
    const int b   = row >> 11;
    const int q   = row & (T_ - 1);
    float* Sr = S + (size_t)b * T_ * T_ + (size_t)q * T_;
    const int L = q + 1;
    const int Lpad = (q & ~127) + 128;
    const int tid = threadIdx.x;

    __shared__ float red[8];

    float m = -INFINITY;
    for (int k = tid; k < L; k += 256) m = fmaxf(m, Sr[k]);
    #pragma unroll
    for (int o = 16; o > 0; o >>= 1) m = fmaxf(m, __shfl_xor_sync(0xFFFFFFFFu, m, o));
    if ((tid & 31) == 0) red[tid >> 5] = m;
    __syncthreads();
    float m_all = red[0];
    #pragma unroll
    for (int i = 1; i < 8; i++) m_all = fmaxf(m_all, red[i]);
    __syncthreads();

    float ssum = 0.0f;
    for (int k = tid; k < L; k += 256) {
        float e = __expf(Sr[k] - m_all);
        Sr[k] = e;
        ssum += e;
    }
    #pragma unroll
    for (int o = 16; o > 0; o >>= 1) ssum += __shfl_xor_sync(0xFFFFFFFFu, ssum, o);
    if ((tid & 31) == 0) red[tid >> 5] = ssum;
    __syncthreads();
    float s_all = 0.0f;
    #pragma unroll
    for (int i = 0; i < 8; i++) s_all += red[i];
    const float inv = 1.0f / s_all;

    for (int k = tid; k < Lpad; k += 256)
        Sr[k] = (k < L) ? Sr[k] * inv : 0.0f;
}

// ---------------------------------------------------------------------------
// Launch
// ---------------------------------------------------------------------------
extern "C" void kernel_launch(void* const* d_in, const int* in_sizes, int n_in,
                              void* d_out, int out_size)
{
    const float* x  = (const float*)d_in[0];   // [B, T, C]
    const float* Wq = (const float*)d_in[1];   // [C, H]
    const float* Wk = (const float*)d_in[2];   // [C, H]
    const float* Wv = (const float*)d_in[3];   // [C, H]
    float* out = (float*)d_out;                // [B, T, H]

    float *qp, *kp, *vp, *vtp, *sp, *wtp;
    cudaGetSymbolAddress((void**)&qp,  g_Q);
    cudaGetSymbolAddress((void**)&kp,  g_K);
    cudaGetSymbolAddress((void**)&vp,  g_V);
    cudaGetSymbolAddress((void**)&vtp, g_VT);
    cudaGetSymbolAddress((void**)&sp,  g_S);
    cudaGetSymbolAddress((void**)&wtp, g_WT);

    // W transposes: [C,H] -> [H,C]
    dim3 gtw(H_ / 32, C_ / 32, 1);
    transpose_k<<<gtw, 256>>>(Wq, wtp + 0 * (size_t)H_ * C_, C_, H_);
    transpose_k<<<gtw, 256>>>(Wk, wtp + 1 * (size_t)H_ * C_, C_, H_);
    transpose_k<<<gtw, 256>>>(Wv, wtp + 2 * (size_t)H_ * C_, C_, H_);

    // Projections
    dim3 gproj(H_ / 128, (B_ * T_) / 128);
    proj_mma<<<gproj, 256>>>(x, wtp + 0 * (size_t)H_ * C_, qp);
    proj_mma<<<gproj, 256>>>(x, wtp + 1 * (size_t)H_ * C_, kp);
    proj_mma<<<gproj, 256>>>(x, wtp + 2 * (size_t)H_ * C_, vp);

    // V transpose per batch: [T,H] -> [H,T]
    dim3 gtv(H_ / 32, T_ / 32, B_);
    transpose_k<<<gtv, 256>>>(vp, vtp, T_, H_);

    // Scores (causal blocks only)
    dim3 gqk(T_ / 128, T_ / 128, B_);
    qk_mma<<<gqk, 256>>>();

    // Softmax
    softmax_causal<<<B_ * T_, 256>>>(sp);

    // Output
    dim3 gpv(H_ / 128, T_ / 128, B_);
    pv_mma<<<gpv, 256>>>(out);
}

// round 4
// speedup vs baseline: 3.2076x; 1.0610x over previous
#include <cuda_runtime.h>
#include <cstdint>
#include <math.h>

#define B_  8
#define T_  2048
#define C_  1024
#define H_  1024
#define SCALE_ (1.0f / 32.0f)   // 1/sqrt(1024)

// GEMM tiling
#define BM 256
#define BN 128
#define BK 32
#define LDS_W 36                         // padded row stride (words)
#define A_ST_BYTES (BM * LDS_W * 4)      // 36864
#define B_ST_BYTES (BN * LDS_W * 4)      // 18432
#define STAGE_BYTES (A_ST_BYTES + B_ST_BYTES)
#define NSTAGES 3
#define SMEM_TOTAL (STAGE_BYTES * NSTAGES)   // 165888

// ---------------------------------------------------------------------------
// Scratch (device globals)
// ---------------------------------------------------------------------------
__device__ float g_X [(size_t)B_ * T_ * C_];   // 64 MB  x pre-rounded to tf32
__device__ float g_Q [(size_t)B_ * T_ * H_];   // 64 MB
__device__ float g_K [(size_t)B_ * T_ * H_];   // 64 MB
__device__ float g_V [(size_t)B_ * T_ * H_];   // 64 MB
__device__ float g_VT[(size_t)B_ * H_ * T_];   // 64 MB
__device__ float g_S [(size_t)B_ * T_ * T_];   // 128 MB
__device__ float g_WT[3][(size_t)H_ * C_];     // 12 MB  W^T, tf32-rounded

// ---------------------------------------------------------------------------
// Helpers
// ---------------------------------------------------------------------------
__device__ __forceinline__ uint32_t f2tf32(float f) {
    uint32_t r;
    asm("cvt.rna.tf32.f32 %0, %1;" : "=r"(r) : "f"(f));
    return r;
}
__device__ __forceinline__ float round_tf32(float f) {
    return __uint_as_float(f2tf32(f));
}
__device__ __forceinline__ void mma_tf32(float c[4], const uint32_t a[4],
                                         const uint32_t b[2]) {
    asm volatile(
        "mma.sync.aligned.m16n8k8.row.col.f32.tf32.tf32.f32 "
        "{%0,%1,%2,%3}, {%4,%5,%6,%7}, {%8,%9}, {%0,%1,%2,%3};"
        : "+f"(c[0]), "+f"(c[1]), "+f"(c[2]), "+f"(c[3])
        : "r"(a[0]), "r"(a[1]), "r"(a[2]), "r"(a[3]), "r"(b[0]), "r"(b[1]));
}
__device__ __forceinline__ void cp16(uint32_t d, const void* s) {
    asm volatile("cp.async.cg.shared.global [%0], [%1], 16;" :: "r"(d), "l"(s));
}
__device__ __forceinline__ void cp_commit() { asm volatile("cp.async.commit_group;"); }
__device__ __forceinline__ void cp_wait1()  { asm volatile("cp.async.wait_group 1;"); }
__device__ __forceinline__ void cp_wait0()  { asm volatile("cp.async.wait_group 0;"); }

// ---------------------------------------------------------------------------
// GEMM core: C[BM,BN] (+)= A[BM, BK*nt] @ B[BN, BK*nt]^T, both K-major,
// inputs already tf32-rounded. 256 thr = 8 warps (4m x 2n), warp tile 64x64.
// 3-stage cp.async pipeline. Dynamic SMEM = SMEM_TOTAL.
// ---------------------------------------------------------------------------
__device__ __forceinline__ void gemm_core(const float* __restrict__ Ag, int lda,
                                          const float* __restrict__ Bg, int ldb,
                                          float* __restrict__ Cg, int ldc,
                                          int nt, float scale, bool round_out)
{
    extern __shared__ char dynsmem[];
    const int tid  = threadIdx.x;
    const int lane = tid & 31;
    const int wid  = tid >> 5;
    const int wm   = wid & 3;      // m-warp 0..3 (64 rows each)
    const int wn   = wid >> 2;     // n-warp 0..1 (64 cols each)
    const int g    = lane >> 2;    // 0..7
    const int t    = lane & 3;     // 0..3

    const uint32_t sb = (uint32_t)__cvta_generic_to_shared(dynsmem);
    const int r0   = tid >> 3;          // 0..31
    const int c16  = (tid & 7) << 4;    // byte offset 0..112
    const int cflt = (tid & 7) << 2;    // float offset

    // issue cp.async for k-tile s into buffer buf
    auto issue = [&](int s, int buf) {
        const float* Abase = Ag + (size_t)s * BK;
        const float* Bbase = Bg + (size_t)s * BK;
        const uint32_t ab = sb + buf * STAGE_BYTES;
        const uint32_t bb = ab + A_ST_BYTES;
        #pragma unroll
        for (int i = 0; i < 8; i++) {
            int r = r0 + 32 * i;
            cp16(ab + r * (LDS_W * 4) + c16, Abase + (size_t)r * lda + cflt);
        }
        #pragma unroll
        for (int i = 0; i < 4; i++) {
            int r = r0 + 32 * i;
            cp16(bb + r * (LDS_W * 4) + c16, Bbase + (size_t)r * ldb + cflt);
        }
        cp_commit();
    };

    float acc[4][8][4];
    #pragma unroll
    for (int i = 0; i < 4; i++)
        #pragma unroll
        for (int j = 0; j < 8; j++)
            #pragma unroll
            for (int r = 0; r < 4; r++) acc[i][j][r] = 0.0f;

    issue(0, 0);
    issue(1, 1);

    const int mwb = wm * 64;
    const int nwb = wn * 64;

    for (int s = 0; s < nt; s++) {
        if (s + 1 < nt) cp_wait1(); else cp_wait0();
        __syncthreads();
        if (s + 2 < nt) issue(s + 2, (s + 2) % NSTAGES);

        const uint32_t* As = (const uint32_t*)(dynsmem + (s % NSTAGES) * STAGE_BYTES);
        const uint32_t* Bs = (const uint32_t*)(dynsmem + (s % NSTAGES) * STAGE_BYTES + A_ST_BYTES);

        #pragma unroll
        for (int kk = 0; kk < BK; kk += 8) {
            uint32_t ar[4][4];
            #pragma unroll
            for (int mf = 0; mf < 4; mf++) {
                const int rb = mwb + mf * 16;
                ar[mf][0] = As[(rb + g)     * LDS_W + kk + t];
                ar[mf][1] = As[(rb + g + 8) * LDS_W + kk + t];
                ar[mf][2] = As[(rb + g)     * LDS_W + kk + t + 4];
                ar[mf][3] = As[(rb + g + 8) * LDS_W + kk + t + 4];
            }
            uint32_t br[8][2];
            #pragma unroll
            for (int nf = 0; nf < 8; nf++) {
                const int cb = nwb + nf * 8;
                br[nf][0] = Bs[(cb + g) * LDS_W + kk + t];
                br[nf][1] = Bs[(cb + g) * LDS_W + kk + t + 4];
            }
            #pragma unroll
            for (int mf = 0; mf < 4; mf++)
                #pragma unroll
                for (int nf = 0; nf < 8; nf++)
                    mma_tf32(acc[mf][nf], ar[mf], br[nf]);
        }
        __syncthreads();
    }

    // Epilogue
    #pragma unroll
    for (int mf = 0; mf < 4; mf++) {
        const int row = mwb + mf * 16 + g;
        #pragma unroll
        for (int nf = 0; nf < 8; nf++) {
            const int col = nwb + nf * 8 + 2 * t;
            float v0 = acc[mf][nf][0] * scale, v1 = acc[mf][nf][1] * scale;
            float v2 = acc[mf][nf][2] * scale, v3 = acc[mf][nf][3] * scale;
            if (round_out) {
                v0 = round_tf32(v0); v1 = round_tf32(v1);
                v2 = round_tf32(v2); v3 = round_tf32(v3);
            }
            *(float2*)&Cg[(size_t)row * ldc + col]       = make_float2(v0, v1);
            *(float2*)&Cg[(size_t)(row + 8) * ldc + col] = make_float2(v2, v3);
        }
    }
}

// ---------------------------------------------------------------------------
// GEMM kernel wrappers
// ---------------------------------------------------------------------------
__global__ __launch_bounds__(256, 1)
void proj_mma(const float* __restrict__ A, const float* __restrict__ WT,
              float* __restrict__ out)
{
    const size_t m0 = (size_t)blockIdx.y * BM;
    const size_t n0 = (size_t)blockIdx.x * BN;
    gemm_core(A + m0 * C_, C_, WT + n0 * C_, C_,
              out + m0 * H_ + n0, H_, C_ / BK, 1.0f, true);
}

__global__ __launch_bounds__(256, 1)
void qk_mma()
{
    const int kb = blockIdx.x, qb = blockIdx.y;
    if (kb * 128 >= (qb + 1) * 256) return;   // fully masked
    const int b = blockIdx.z;
    const size_t q0 = (size_t)qb * 256, n0 = (size_t)kb * 128;
    gemm_core(g_Q + (size_t)b * T_ * H_ + q0 * H_, H_,
              g_K + (size_t)b * T_ * H_ + n0 * H_, H_,
              g_S + (size_t)b * T_ * T_ + q0 * T_ + n0, T_,
              H_ / BK, SCALE_, false);
}

__global__ __launch_bounds__(256, 1)
void pv_mma(float* __restrict__ out)
{
    const int nb = blockIdx.x, qb = blockIdx.y, b = blockIdx.z;
    const size_t q0 = (size_t)qb * 256, n0 = (size_t)nb * 128;
    gemm_core(g_S  + (size_t)b * T_ * T_ + q0 * T_, T_,
              g_VT + (size_t)b * H_ * T_ + n0 * T_, T_,
              out + (size_t)b * T_ * H_ + q0 * H_ + n0, H_,
              (qb + 1) * 8, 1.0f, false);
}

// ---------------------------------------------------------------------------
// Elementwise convert x -> tf32-rounded copy
// ---------------------------------------------------------------------------
__global__ __launch_bounds__(256)
void cvt_x(const float* __restrict__ in, float* __restrict__ out)
{
    const size_t i = ((size_t)blockIdx.x * 256 + threadIdx.x) * 4;
    float4 v = *(const float4*)(in + i);
    v.x = round_tf32(v.x); v.y = round_tf32(v.y);
    v.z = round_tf32(v.z); v.w = round_tf32(v.w);
    *(float4*)(out + i) = v;
}

// ---------------------------------------------------------------------------
// 32x32 tiled transpose, optional tf32 rounding on store
// ---------------------------------------------------------------------------
template<bool ROUND>
__global__ __launch_bounds__(256)
void transpose_k(const float* __restrict__ in, float* __restrict__ out,
                 int rows, int cols)
{
    __shared__ float tile[32][33];
    const int z = blockIdx.z;
    const float* I = in  + (size_t)z * rows * cols;
    float*       O = out + (size_t)z * rows * cols;
    const int r0 = blockIdx.y * 32, c0 = blockIdx.x * 32;
    const int tx = threadIdx.x & 31, ty = threadIdx.x >> 5;
    #pragma unroll
    for (int i = 0; i < 32; i += 8)
        tile[ty + i][tx] = I[(size_t)(r0 + ty + i) * cols + c0 + tx];
    __syncthreads();
    #pragma unroll
    for (int i = 0; i < 32; i += 8) {
        float v = tile[tx][ty + i];
        if (ROUND) v = round_tf32(v);
        O[(size_t)(c0 + ty + i) * rows + r0 + tx] = v;
    }
}

// ---------------------------------------------------------------------------
// Causal row softmax in place. Zeroes tail to the 256-block bound (pv q-tile),
// and rounds P to tf32 so pv_mma can consume raw bits.
// ---------------------------------------------------------------------------
__global__ __launch_bounds__(256)
void softmax_causal(float* __restrict__ S)
{
    const int row = blockIdx.x;
    const int b   = row >> 11;
    const int q   = row & (T_ - 1);
    float* Sr = S + (size_t)b * T_ * T_ + (size_t)q * T_;
    const int L = q + 1;
    const int Lpad = (q & ~255) + 256;
    const int tid = threadIdx.x;

    __shared__ float red[8];

    float m = -INFINITY;
    for (int k = tid; k < L; k += 256) m = fmaxf(m, Sr[k]);
    #pragma unroll
    for (int o = 16; o > 0; o >>= 1) m = fmaxf(m, __shfl_xor_sync(0xFFFFFFFFu, m, o));
    if ((tid & 31) == 0) red[tid >> 5] = m;
    __syncthreads();
    float m_all = red[0];
    #pragma unroll
    for (int i = 1; i < 8; i++) m_all = fmaxf(m_all, red[i]);
    __syncthreads();

    float ssum = 0.0f;
    for (int k = tid; k < L; k += 256) {
        float e = __expf(Sr[k] - m_all);
        Sr[k] = e;
        ssum += e;
    }
    #pragma unroll
    for (int o = 16; o > 0; o >>= 1) ssum += __shfl_xor_sync(0xFFFFFFFFu, ssum, o);
    if ((tid & 31) == 0) red[tid >> 5] = ssum;
    __syncthreads();
    float s_all = 0.0f;
    #pragma unroll
    for (int i = 0; i < 8; i++) s_all += red[i];
    const float inv = 1.0f / s_all;

    for (int k = tid; k < Lpad; k += 256)
        Sr[k] = (k < L) ? round_tf32(Sr[k] * inv) : 0.0f;
}

// ---------------------------------------------------------------------------
// Launch
// ---------------------------------------------------------------------------
extern "C" void kernel_launch(void* const* d_in, const int* in_sizes, int n_in,
                              void* d_out, int out_size)
{
    const float* x  = (const float*)d_in[0];
    const float* Wq = (const float*)d_in[1];
    const float* Wk = (const float*)d_in[2];
    const float* Wv = (const float*)d_in[3];
    float* out = (float*)d_out;

    float *xp, *qp, *kp, *vp, *vtp, *sp, *wtp;
    cudaGetSymbolAddress((void**)&xp,  g_X);
    cudaGetSymbolAddress((void**)&qp,  g_Q);
    cudaGetSymbolAddress((void**)&kp,  g_K);
    cudaGetSymbolAddress((void**)&vp,  g_V);
    cudaGetSymbolAddress((void**)&vtp, g_VT);
    cudaGetSymbolAddress((void**)&sp,  g_S);
    cudaGetSymbolAddress((void**)&wtp, g_WT);

    cudaFuncSetAttribute(proj_mma, cudaFuncAttributeMaxDynamicSharedMemorySize, SMEM_TOTAL);
    cudaFuncSetAttribute(qk_mma,   cudaFuncAttributeMaxDynamicSharedMemorySize, SMEM_TOTAL);
    cudaFuncSetAttribute(pv_mma,   cudaFuncAttributeMaxDynamicSharedMemorySize, SMEM_TOTAL);

    // x -> tf32-rounded copy
    cvt_x<<<(B_ * T_ * C_) / (256 * 4), 256>>>(x, xp);

    // W transposes with tf32 rounding: [C,H] -> [H,C]
    dim3 gtw(H_ / 32, C_ / 32, 1);
    transpose_k<true><<<gtw, 256>>>(Wq, wtp + 0 * (size_t)H_ * C_, C_, H_);
    transpose_k<true><<<gtw, 256>>>(Wk, wtp + 1 * (size_t)H_ * C_, C_, H_);
    transpose_k<true><<<gtw, 256>>>(Wv, wtp + 2 * (size_t)H_ * C_, C_, H_);

    // Projections (epilogue rounds Q/K/V to tf32)
    dim3 gproj(H_ / BN, (B_ * T_) / BM);
    proj_mma<<<gproj, 256, SMEM_TOTAL>>>(xp, wtp + 0 * (size_t)H_ * C_, qp);
    proj_mma<<<gproj, 256, SMEM_TOTAL>>>(xp, wtp + 1 * (size_t)H_ * C_, kp);
    proj_mma<<<gproj, 256, SMEM_TOTAL>>>(xp, wtp + 2 * (size_t)H_ * C_, vp);

    // V transpose (V already tf32-rounded)
    dim3 gtv(H_ / 32, T_ / 32, B_);
    transpose_k<false><<<gtv, 256>>>(vp, vtp, T_, H_);

    // Scores (q-tile 256, k-tile 128, causal block skip)
    dim3 gqk(T_ / 128, T_ / 256, B_);
    qk_mma<<<gqk, 256, SMEM_TOTAL>>>();

    // Softmax (rounds P to tf32, zeroes tail to 256 bound)
    softmax_causal<<<B_ * T_, 256>>>(sp);

    // Output
    dim3 gpv(H_ / 128, T_ / 256, B_);
    pv_mma<<<gpv, 256, SMEM_TOTAL>>>(out);
}

// round 5
// speedup vs baseline: 4.1774x; 1.3023x over previous
#include <cuda_runtime.h>
#include <cstdint>
#include <math.h>

#define B_  8
#define T_  2048
#define C_  1024
#define H_  1024
#define SCALE_ (1.0f / 32.0f)

// GEMM tiling
#define BM 128
#define BN 128
#define BK 32
#define NTHR 128
#define A_ST_BYTES 16384                 // 128 rows x 32 words x 4
#define STAGE_BYTES 32768                // A + B
#define NSTAGES 3
#define SMEM_TOTAL (STAGE_BYTES * NSTAGES)   // 98304 -> 2 CTAs/SM

// pos(k) within an 8-group for the pair-permuted K layout
__host__ __device__ __forceinline__ int kperm(int k) {
    return (k & ~7) | (((k & 3) << 1) | ((k & 7) >> 2));
}

// ---------------------------------------------------------------------------
// Scratch (device globals) — all GEMM operands stored K-pair-permuted
// ---------------------------------------------------------------------------
__device__ float g_X [(size_t)B_ * T_ * C_];
__device__ float g_Q [(size_t)B_ * T_ * H_];
__device__ float g_K [(size_t)B_ * T_ * H_];
__device__ float g_V [(size_t)B_ * T_ * H_];   // h unpermuted (feeds transpose)
__device__ float g_VT[(size_t)B_ * H_ * T_];
__device__ float g_S [(size_t)B_ * T_ * T_];
__device__ float g_WT[3][(size_t)H_ * C_];

// ---------------------------------------------------------------------------
// Helpers
// ---------------------------------------------------------------------------
__device__ __forceinline__ uint32_t f2tf32(float f) {
    uint32_t r;
    asm("cvt.rna.tf32.f32 %0, %1;" : "=r"(r) : "f"(f));
    return r;
}
__device__ __forceinline__ float round_tf32(float f) {
    return __uint_as_float(f2tf32(f));
}
__device__ __forceinline__ void mma_tf32(float c[4], const uint32_t a[4],
                                         const uint32_t b[2]) {
    asm volatile(
        "mma.sync.aligned.m16n8k8.row.col.f32.tf32.tf32.f32 "
        "{%0,%1,%2,%3}, {%4,%5,%6,%7}, {%8,%9}, {%0,%1,%2,%3};"
        : "+f"(c[0]), "+f"(c[1]), "+f"(c[2]), "+f"(c[3])
        : "r"(a[0]), "r"(a[1]), "r"(a[2]), "r"(a[3]), "r"(b[0]), "r"(b[1]));
}
__device__ __forceinline__ void cp16(uint32_t d, const void* s) {
    asm volatile("cp.async.cg.shared.global [%0], [%1], 16;" :: "r"(d), "l"(s));
}
__device__ __forceinline__ void cp_commit() { asm volatile("cp.async.commit_group;"); }
__device__ __forceinline__ void cp_wait1()  { asm volatile("cp.async.wait_group 1;"); }
__device__ __forceinline__ void cp_wait0()  { asm volatile("cp.async.wait_group 0;"); }

// ---------------------------------------------------------------------------
// GEMM core: C[128,128] = A[128, 32*nt] @ B[128, 32*nt]^T, K-major, inputs
// tf32-rounded AND K-pair-permuted. 128 thr = 4 warps (2m x 2n), warp 64x64.
// Swizzled 32-word SMEM rows, 3-stage cp.async, LDS.64 fragment loads.
// ---------------------------------------------------------------------------
__device__ __forceinline__ void gemm_core(const float* __restrict__ Ag, int lda,
                                          const float* __restrict__ Bg, int ldb,
                                          float* __restrict__ Cg, int ldc,
                                          int nt, float scale,
                                          bool round_out, bool permute_out)
{
    extern __shared__ char dynsmem[];
    const int tid  = threadIdx.x;
    const int lane = tid & 31;
    const int wid  = tid >> 5;
    const int wm   = wid & 1;
    const int wn   = wid >> 1;
    const int g    = lane >> 2;
    const int t    = lane & 3;

    const uint32_t sb = (uint32_t)__cvta_generic_to_shared(dynsmem);
    const int r0 = tid >> 3;            // 0..15
    const int c4 = (tid & 7) << 2;      // word col 0,4,...,28

    auto issue = [&](int s, int buf) {
        const float* Abase = Ag + (size_t)s * BK;
        const float* Bbase = Bg + (size_t)s * BK;
        const uint32_t ab = sb + buf * STAGE_BYTES;
        const uint32_t bb = ab + A_ST_BYTES;
        #pragma unroll
        for (int i = 0; i < 8; i++) {
            const int r  = r0 + 16 * i;
            const int sc = c4 ^ ((r & 3) << 3);
            cp16(ab + r * 128 + sc * 4, Abase + (size_t)r * lda + c4);
            cp16(bb + r * 128 + sc * 4, Bbase + (size_t)r * ldb + c4);
        }
        cp_commit();
    };

    float acc[4][8][4];
    #pragma unroll
    for (int i = 0; i < 4; i++)
        #pragma unroll
        for (int j = 0; j < 8; j++)
            #pragma unroll
            for (int r = 0; r < 4; r++) acc[i][j][r] = 0.0f;

    issue(0, 0);
    issue(1, 1);

    const int mwb = wm * 64;
    const int nwb = wn * 64;
    const int swz = (g & 3) << 3;       // fragment-col XOR term (row&3 == g&3)

    for (int s = 0; s < nt; s++) {
        if (s + 1 < nt) cp_wait1(); else cp_wait0();
        __syncthreads();
        if (s + 2 < nt) issue(s + 2, (s + 2) % NSTAGES);

        const uint32_t* As = (const uint32_t*)(dynsmem + (s % NSTAGES) * STAGE_BYTES);
        const uint32_t* Bs = (const uint32_t*)(dynsmem + (s % NSTAGES) * STAGE_BYTES + A_ST_BYTES);

        #pragma unroll
        for (int kk = 0; kk < BK; kk += 8) {
            const int cw = (kk + 2 * t) ^ swz;
            uint32_t ar[4][4];
            #pragma unroll
            for (int mf = 0; mf < 4; mf++) {
                const int rA = mwb + mf * 16 + g;
                uint2 v0 = *(const uint2*)&As[rA * 32 + cw];        // (a0,a2)
                uint2 v1 = *(const uint2*)&As[(rA + 8) * 32 + cw];  // (a1,a3)
                ar[mf][0] = v0.x; ar[mf][2] = v0.y;
                ar[mf][1] = v1.x; ar[mf][3] = v1.y;
            }
            uint32_t br[8][2];
            #pragma unroll
            for (int nf = 0; nf < 8; nf++) {
                const int rB = nwb + nf * 8 + g;
                uint2 v = *(const uint2*)&Bs[rB * 32 + cw];         // (b0,b1)
                br[nf][0] = v.x; br[nf][1] = v.y;
            }
            #pragma unroll
            for (int mf = 0; mf < 4; mf++)
                #pragma unroll
                for (int nf = 0; nf < 8; nf++)
                    mma_tf32(acc[mf][nf], ar[mf], br[nf]);
        }
        __syncthreads();
    }

    #pragma unroll
    for (int mf = 0; mf < 4; mf++) {
        const int row = mwb + mf * 16 + g;
        #pragma unroll
        for (int nf = 0; nf < 8; nf++) {
            const int col = nwb + nf * 8 + 2 * t;
            float v0 = acc[mf][nf][0] * scale, v1 = acc[mf][nf][1] * scale;
            float v2 = acc[mf][nf][2] * scale, v3 = acc[mf][nf][3] * scale;
            if (round_out) {
                v0 = round_tf32(v0); v1 = round_tf32(v1);
                v2 = round_tf32(v2); v3 = round_tf32(v3);
            }
            if (permute_out) {
                const int p0 = kperm(col), p1 = kperm(col + 1);
                Cg[(size_t)row * ldc + p0]       = v0;
                Cg[(size_t)row * ldc + p1]       = v1;
                Cg[(size_t)(row + 8) * ldc + p0] = v2;
                Cg[(size_t)(row + 8) * ldc + p1] = v3;
            } else {
                *(float2*)&Cg[(size_t)row * ldc + col]       = make_float2(v0, v1);
                *(float2*)&Cg[(size_t)(row + 8) * ldc + col] = make_float2(v2, v3);
            }
        }
    }
}

// ---------------------------------------------------------------------------
// GEMM wrappers
// ---------------------------------------------------------------------------
__global__ __launch_bounds__(NTHR, 2)
void proj_mma(const float* __restrict__ A, const float* __restrict__ WT,
              float* __restrict__ out, int permute)
{
    const size_t m0 = (size_t)blockIdx.y * BM;
    const size_t n0 = (size_t)blockIdx.x * BN;
    gemm_core(A + m0 * C_, C_, WT + n0 * C_, C_,
              out + m0 * H_ + n0, H_, C_ / BK, 1.0f, true, permute != 0);
}

__global__ __launch_bounds__(NTHR, 2)
void qk_mma()
{
    const int kb = blockIdx.x, qb = blockIdx.y;
    if (kb > qb) return;
    const int b = blockIdx.z;
    const size_t q0 = (size_t)qb * 128, n0 = (size_t)kb * 128;
    gemm_core(g_Q + (size_t)b * T_ * H_ + q0 * H_, H_,
              g_K + (size_t)b * T_ * H_ + n0 * H_, H_,
              g_S + (size_t)b * T_ * T_ + q0 * T_ + n0, T_,
              H_ / BK, SCALE_, false, false);
}

__global__ __launch_bounds__(NTHR, 2)
void pv_mma(float* __restrict__ out)
{
    const int nb = blockIdx.x, qb = blockIdx.y, b = blockIdx.z;
    const size_t q0 = (size_t)qb * 128, n0 = (size_t)nb * 128;
    gemm_core(g_S  + (size_t)b * T_ * T_ + q0 * T_, T_,
              g_VT + (size_t)b * H_ * T_ + n0 * T_, T_,
              out + (size_t)b * T_ * H_ + q0 * H_ + n0, H_,
              (qb + 1) * 4, 1.0f, false, false);
}

// ---------------------------------------------------------------------------
// x -> tf32-rounded, K-pair-permuted copy
// ---------------------------------------------------------------------------
__global__ __launch_bounds__(256)
void cvt_x(const float* __restrict__ in, float* __restrict__ out)
{
    const size_t i = ((size_t)blockIdx.x * 256 + threadIdx.x) * 4;
    float4 v = *(const float4*)(in + i);
    const size_t base = i & ~(size_t)7;
    const int k0 = (int)(i & 7);          // 0 or 4
    out[base + kperm(k0 + 0)] = round_tf32(v.x);
    out[base + kperm(k0 + 1)] = round_tf32(v.y);
    out[base + kperm(k0 + 2)] = round_tf32(v.z);
    out[base + kperm(k0 + 3)] = round_tf32(v.w);
}

// ---------------------------------------------------------------------------
// 32x32 transpose; output fast dim (the GEMM K dim) pair-permuted.
// ---------------------------------------------------------------------------
template<bool ROUND>
__global__ __launch_bounds__(256)
void transpose_k(const float* __restrict__ in, float* __restrict__ out,
                 int rows, int cols)
{
    __shared__ float tile[32][33];
    const int z = blockIdx.z;
    const float* I = in  + (size_t)z * rows * cols;
    float*       O = out + (size_t)z * rows * cols;
    const int r0 = blockIdx.y * 32, c0 = blockIdx.x * 32;
    const int tx = threadIdx.x & 31, ty = threadIdx.x >> 5;
    #pragma unroll
    for (int i = 0; i < 32; i += 8)
        tile[ty + i][tx] = I[(size_t)(r0 + ty + i) * cols + c0 + tx];
    __syncthreads();
    const int fp = kperm(r0 + tx);     // permuted fast index
    #pragma unroll
    for (int i = 0; i < 32; i += 8) {
        float v = tile[tx][ty + i];
        if (ROUND) v = round_tf32(v);
        O[(size_t)(c0 + ty + i) * rows + fp] = v;
    }
}

// ---------------------------------------------------------------------------
// Causal softmax: reads S (normal layout), writes P tf32-rounded and
// K-pair-permuted, zero tail to 128 bound. float4 vectorized.
// ---------------------------------------------------------------------------
__global__ __launch_bounds__(256)
void softmax_causal(float* __restrict__ S)
{
    const int row = blockIdx.x;
    const int b   = row >> 11;
    const int q   = row & (T_ - 1);
    float* Sr = S + (size_t)b * T_ * T_ + (size_t)q * T_;
    const int L = q + 1;
    const int Lpad = (q & ~127) + 128;
    const int tid = threadIdx.x;

    __shared__ float red[8];

    // Pass 1: max (mask per element)
    float m = -INFINITY;
    for (int k = tid * 4; k < Lpad; k += 1024) {
        float4 v = *(const float4*)&Sr[k];
        if (k + 0 < L) m = fmaxf(m, v.x);
        if (k + 1 < L) m = fmaxf(m, v.y);
        if (k + 2 < L) m = fmaxf(m, v.z);
        if (k + 3 < L) m = fmaxf(m, v.w);
    }
    #pragma unroll
    for (int o = 16; o > 0; o >>= 1) m = fmaxf(m, __shfl_xor_sync(0xFFFFFFFFu, m, o));
    if ((tid & 31) == 0) red[tid >> 5] = m;
    __syncthreads();
    float m_all = red[0];
    #pragma unroll
    for (int i = 1; i < 8; i++) m_all = fmaxf(m_all, red[i]);
    __syncthreads();

    // Pass 2: e = exp(v - max) (0 beyond L), write back, accumulate sum
    float ssum = 0.0f;
    for (int k = tid * 4; k < Lpad; k += 1024) {
        float4 v = *(const float4*)&Sr[k];
        float4 e;
        e.x = (k + 0 < L) ? __expf(v.x - m_all) : 0.0f;
        e.y = (k + 1 < L) ? __expf(v.y - m_all) : 0.0f;
        e.z = (k + 2 < L) ? __expf(v.z - m_all) : 0.0f;
        e.w = (k + 3 < L) ? __expf(v.w - m_all) : 0.0f;
        *(float4*)&Sr[k] = e;
        ssum += e.x + e.y + e.z + e.w;
    }
    #pragma unroll
    for (int o = 16; o > 0; o >>= 1) ssum += __shfl_xor_sync(0xFFFFFFFFu, ssum, o);
    if ((tid & 31) == 0) red[tid >> 5] = ssum;
    __syncthreads();
    float s_all = 0.0f;
    #pragma unroll
    for (int i = 0; i < 8; i++) s_all += red[i];
    const float inv = 1.0f / s_all;
    __syncthreads();

    // Pass 3: normalize + tf32-round + pair-permute in place.
    // Each 8-group is owned by two ADJACENT threads (same warp): read-all,
    // __syncwarp, then scatter within the group. Lpad % 128 == 0 keeps warps
    // convergent at the __syncwarp.
    for (int k = tid * 4; k < Lpad; k += 1024) {
        float4 v = *(const float4*)&Sr[k];
        __syncwarp();
        const int base = k & ~7;
        const int k0   = k & 7;          // 0 or 4
        Sr[base + kperm(k0 + 0)] = round_tf32(v.x * inv);
        Sr[base + kperm(k0 + 1)] = round_tf32(v.y * inv);
        Sr[base + kperm(k0 + 2)] = round_tf32(v.z * inv);
        Sr[base + kperm(k0 + 3)] = round_tf32(v.w * inv);
    }
}

// ---------------------------------------------------------------------------
// Launch
// ---------------------------------------------------------------------------
extern "C" void kernel_launch(void* const* d_in, const int* in_sizes, int n_in,
                              void* d_out, int out_size)
{
    const float* x  = (const float*)d_in[0];
    const float* Wq = (const float*)d_in[1];
    const float* Wk = (const float*)d_in[2];
    const float* Wv = (const float*)d_in[3];
    float* out = (float*)d_out;

    float *xp, *qp, *kp, *vp, *vtp, *sp, *wtp;
    cudaGetSymbolAddress((void**)&xp,  g_X);
    cudaGetSymbolAddress((void**)&qp,  g_Q);
    cudaGetSymbolAddress((void**)&kp,  g_K);
    cudaGetSymbolAddress((void**)&vp,  g_V);
    cudaGetSymbolAddress((void**)&vtp, g_VT);
    cudaGetSymbolAddress((void**)&sp,  g_S);
    cudaGetSymbolAddress((void**)&wtp, g_WT);

    cudaFuncSetAttribute(proj_mma, cudaFuncAttributeMaxDynamicSharedMemorySize, SMEM_TOTAL);
    cudaFuncSetAttribute(qk_mma,   cudaFuncAttributeMaxDynamicSharedMemorySize, SMEM_TOTAL);
    cudaFuncSetAttribute(pv_mma,   cudaFuncAttributeMaxDynamicSharedMemorySize, SMEM_TOTAL);

    cvt_x<<<(B_ * T_ * C_) / (256 * 4), 256>>>(x, xp);

    dim3 gtw(H_ / 32, C_ / 32, 1);
    transpose_k<true><<<gtw, 256>>>(Wq, wtp + 0 * (size_t)H_ * C_, C_, H_);
    transpose_k<true><<<gtw, 256>>>(Wk, wtp + 1 * (size_t)H_ * C_, C_, H_);
    transpose_k<true><<<gtw, 256>>>(Wv, wtp + 2 * (size_t)H_ * C_, C_, H_);

    dim3 gproj(H_ / BN, (B_ * T_) / BM);
    proj_mma<<<gproj, NTHR, SMEM_TOTAL>>>(xp, wtp + 0 * (size_t)H_ * C_, qp, 1);
    proj_mma<<<gproj, NTHR, SMEM_TOTAL>>>(xp, wtp + 1 * (size_t)H_ * C_, kp, 1);
    proj_mma<<<gproj, NTHR, SMEM_TOTAL>>>(xp, wtp + 2 * (size_t)H_ * C_, vp, 0);

    dim3 gtv(H_ / 32, T_ / 32, B_);
    transpose_k<false><<<gtv, 256>>>(vp, vtp, T_, H_);

    dim3 gqk(T_ / 128, T_ / 128, B_);
    qk_mma<<<gqk, NTHR, SMEM_TOTAL>>>();

    softmax_causal<<<B_ * T_, 256>>>(sp);

    dim3 gpv(H_ / 128, T_ / 128, B_);
    pv_mma<<<gpv, NTHR, SMEM_TOTAL>>>(out);
}

// round 6
// speedup vs baseline: 4.3057x; 1.0307x over previous
#include <cuda_runtime.h>
#include <cstdint>
#include <math.h>

#define B_  8
#define T_  2048
#define C_  1024
#define H_  1024
#define SCALE_ (1.0f / 32.0f)

// GEMM tiling
#define BM 128
#define BN 128
#define BK 32
#define NTHR 128
#define A_ST_BYTES 16384
#define STAGE_BYTES 32768
#define NSTAGES 3
#define SMEM_TOTAL (STAGE_BYTES * NSTAGES)   // 98304 -> 2 CTAs/SM

__host__ __device__ __forceinline__ int kperm(int k) {
    return (k & ~7) | (((k & 3) << 1) | ((k & 7) >> 2));
}

// ---------------------------------------------------------------------------
// Scratch (device globals) — GEMM operands stored K-pair-permuted
// ---------------------------------------------------------------------------
__device__ float g_X  [(size_t)B_ * T_ * C_];
__device__ float g_Q  [(size_t)B_ * T_ * H_];
__device__ float g_K  [(size_t)B_ * T_ * H_];
__device__ float g_V  [(size_t)B_ * T_ * H_];   // h unpermuted (feeds transpose)
__device__ float g_VT [(size_t)B_ * H_ * T_];
__device__ float g_S  [(size_t)B_ * T_ * T_];
__device__ float g_WT [3][(size_t)H_ * C_];
__device__ float g_inv[(size_t)B_ * T_];        // 1/rowsum for deferred softmax norm

// ---------------------------------------------------------------------------
// Helpers
// ---------------------------------------------------------------------------
__device__ __forceinline__ uint32_t f2tf32(float f) {
    uint32_t r;
    asm("cvt.rna.tf32.f32 %0, %1;" : "=r"(r) : "f"(f));
    return r;
}
__device__ __forceinline__ float round_tf32(float f) {
    return __uint_as_float(f2tf32(f));
}
__device__ __forceinline__ void mma_tf32(float c[4], const uint32_t a[4],
                                         const uint32_t b[2]) {
    asm volatile(
        "mma.sync.aligned.m16n8k8.row.col.f32.tf32.tf32.f32 "
        "{%0,%1,%2,%3}, {%4,%5,%6,%7}, {%8,%9}, {%0,%1,%2,%3};"
        : "+f"(c[0]), "+f"(c[1]), "+f"(c[2]), "+f"(c[3])
        : "r"(a[0]), "r"(a[1]), "r"(a[2]), "r"(a[3]), "r"(b[0]), "r"(b[1]));
}
__device__ __forceinline__ void cp16(uint32_t d, const void* s) {
    asm volatile("cp.async.cg.shared.global [%0], [%1], 16;" :: "r"(d), "l"(s));
}
__device__ __forceinline__ void cp_commit() { asm volatile("cp.async.commit_group;"); }
__device__ __forceinline__ void cp_wait1()  { asm volatile("cp.async.wait_group 1;"); }
__device__ __forceinline__ void cp_wait0()  { asm volatile("cp.async.wait_group 0;"); }

// ---------------------------------------------------------------------------
// GEMM core: C[128,128] = A[128, 32*nt] @ B[128, 32*nt]^T. K-pair-permuted
// tf32 inputs. 4 warps (2m x 2n), warp 64x64, swizzled rows, 3-stage cp.async,
// register-double-buffered fragments.
// rowscale: per-output-row multiplier (deferred softmax norm), may be null.
// ---------------------------------------------------------------------------
__device__ __forceinline__ void gemm_core(const float* __restrict__ Ag, int lda,
                                          const float* __restrict__ Bg, int ldb,
                                          float* __restrict__ Cg, int ldc,
                                          int nt, float scale,
                                          const float* __restrict__ rowscale,
                                          bool round_out, bool permute_out)
{
    extern __shared__ char dynsmem[];
    const int tid  = threadIdx.x;
    const int lane = tid & 31;
    const int wid  = tid >> 5;
    const int wm   = wid & 1;
    const int wn   = wid >> 1;
    const int g    = lane >> 2;
    const int t    = lane & 3;

    const uint32_t sb = (uint32_t)__cvta_generic_to_shared(dynsmem);
    const int r0 = tid >> 3;
    const int c4 = (tid & 7) << 2;

    auto issue = [&](int s, int buf) {
        const float* Abase = Ag + (size_t)s * BK;
        const float* Bbase = Bg + (size_t)s * BK;
        const uint32_t ab = sb + buf * STAGE_BYTES;
        const uint32_t bb = ab + A_ST_BYTES;
        #pragma unroll
        for (int i = 0; i < 8; i++) {
            const int r  = r0 + 16 * i;
            const int sc = c4 ^ ((r & 3) << 3);
            cp16(ab + r * 128 + sc * 4, Abase + (size_t)r * lda + c4);
            cp16(bb + r * 128 + sc * 4, Bbase + (size_t)r * ldb + c4);
        }
        cp_commit();
    };

    float acc[4][8][4];
    #pragma unroll
    for (int i = 0; i < 4; i++)
        #pragma unroll
        for (int j = 0; j < 8; j++)
            #pragma unroll
            for (int r = 0; r < 4; r++) acc[i][j][r] = 0.0f;

    issue(0, 0);
    issue(1, 1);

    const int mwb = wm * 64;
    const int nwb = wn * 64;
    const int swz = (g & 3) << 3;

    uint32_t ar[2][4][4], br[2][8][2];

    for (int s = 0; s < nt; s++) {
        if (s + 1 < nt) cp_wait1(); else cp_wait0();
        __syncthreads();
        if (s + 2 < nt) issue(s + 2, (s + 2) % NSTAGES);

        const uint32_t* As = (const uint32_t*)(dynsmem + (s % NSTAGES) * STAGE_BYTES);
        const uint32_t* Bs = (const uint32_t*)(dynsmem + (s % NSTAGES) * STAGE_BYTES + A_ST_BYTES);

        // fragment loader for k8-step kk8 into buffer pb
        auto ldfrag = [&](int kk8, int pb) {
            const int cw = (kk8 * 8 + 2 * t) ^ swz;
            #pragma unroll
            for (int mf = 0; mf < 4; mf++) {
                const int rA = mwb + mf * 16 + g;
                uint2 v0 = *(const uint2*)&As[rA * 32 + cw];
                uint2 v1 = *(const uint2*)&As[(rA + 8) * 32 + cw];
                ar[pb][mf][0] = v0.x; ar[pb][mf][2] = v0.y;
                ar[pb][mf][1] = v1.x; ar[pb][mf][3] = v1.y;
            }
            #pragma unroll
            for (int nf = 0; nf < 8; nf++) {
                const int rB = nwb + nf * 8 + g;
                uint2 v = *(const uint2*)&Bs[rB * 32 + cw];
                br[pb][nf][0] = v.x; br[pb][nf][1] = v.y;
            }
        };

        ldfrag(0, 0);
        #pragma unroll
        for (int kk8 = 0; kk8 < 4; kk8++) {
            if (kk8 < 3) ldfrag(kk8 + 1, (kk8 + 1) & 1);
            const int pb = kk8 & 1;
            #pragma unroll
            for (int mf = 0; mf < 4; mf++)
                #pragma unroll
                for (int nf = 0; nf < 8; nf++)
                    mma_tf32(acc[mf][nf], ar[pb][mf], br[pb][nf]);
        }
        __syncthreads();
    }

    #pragma unroll
    for (int mf = 0; mf < 4; mf++) {
        const int row = mwb + mf * 16 + g;
        float s0 = scale, s1 = scale;
        if (rowscale) { s0 = rowscale[row]; s1 = rowscale[row + 8]; }
        #pragma unroll
        for (int nf = 0; nf < 8; nf++) {
            const int col = nwb + nf * 8 + 2 * t;
            float v0 = acc[mf][nf][0] * s0, v1 = acc[mf][nf][1] * s0;
            float v2 = acc[mf][nf][2] * s1, v3 = acc[mf][nf][3] * s1;
            if (round_out) {
                v0 = round_tf32(v0); v1 = round_tf32(v1);
                v2 = round_tf32(v2); v3 = round_tf32(v3);
            }
            if (permute_out) {
                const int p0 = kperm(col), p1 = kperm(col + 1);
                Cg[(size_t)row * ldc + p0]       = v0;
                Cg[(size_t)row * ldc + p1]       = v1;
                Cg[(size_t)(row + 8) * ldc + p0] = v2;
                Cg[(size_t)(row + 8) * ldc + p1] = v3;
            } else {
                *(float2*)&Cg[(size_t)row * ldc + col]       = make_float2(v0, v1);
                *(float2*)&Cg[(size_t)(row + 8) * ldc + col] = make_float2(v2, v3);
            }
        }
    }
}

// ---------------------------------------------------------------------------
// GEMM wrappers
// ---------------------------------------------------------------------------
__global__ __launch_bounds__(NTHR, 2)
void proj_mma(const float* __restrict__ W0, const float* __restrict__ W1,
              const float* __restrict__ W2)
{
    const int z = blockIdx.z;
    const float* WT = (z == 0) ? W0 : (z == 1) ? W1 : W2;
    float* out = (z == 0) ? g_Q : (z == 1) ? g_K : g_V;
    const size_t m0 = (size_t)blockIdx.y * BM;
    const size_t n0 = (size_t)blockIdx.x * BN;
    gemm_core(g_X + m0 * C_, C_, WT + n0 * C_, C_,
              out + m0 * H_ + n0, H_, C_ / BK, 1.0f, nullptr, true, z < 2);
}

__global__ __launch_bounds__(NTHR, 2)
void qk_mma()
{
    const int kb = blockIdx.x, qb = blockIdx.y;
    if (kb > qb) return;
    const int b = blockIdx.z;
    const size_t q0 = (size_t)qb * 128, n0 = (size_t)kb * 128;
    gemm_core(g_Q + (size_t)b * T_ * H_ + q0 * H_, H_,
              g_K + (size_t)b * T_ * H_ + n0 * H_, H_,
              g_S + (size_t)b * T_ * T_ + q0 * T_ + n0, T_,
              H_ / BK, SCALE_, nullptr, false, false);
}

__global__ __launch_bounds__(NTHR, 2)
void pv_mma(float* __restrict__ out)
{
    const int nb = blockIdx.x, qb = blockIdx.y, b = blockIdx.z;
    const size_t q0 = (size_t)qb * 128, n0 = (size_t)nb * 128;
    gemm_core(g_S  + (size_t)b * T_ * T_ + q0 * T_, T_,
              g_VT + (size_t)b * H_ * T_ + n0 * T_, T_,
              out + (size_t)b * T_ * H_ + q0 * H_ + n0, H_,
              (qb + 1) * 4, 1.0f, g_inv + (size_t)b * T_ + q0, false, false);
}

// ---------------------------------------------------------------------------
// x -> tf32-rounded, K-pair-permuted copy
// ---------------------------------------------------------------------------
__global__ __launch_bounds__(256)
void cvt_x(const float* __restrict__ in)
{
    const size_t i = ((size_t)blockIdx.x * 256 + threadIdx.x) * 4;
    float4 v = *(const float4*)(in + i);
    const size_t base = i & ~(size_t)7;
    const int k0 = (int)(i & 7);
    g_X[base + kperm(k0 + 0)] = round_tf32(v.x);
    g_X[base + kperm(k0 + 1)] = round_tf32(v.y);
    g_X[base + kperm(k0 + 2)] = round_tf32(v.z);
    g_X[base + kperm(k0 + 3)] = round_tf32(v.w);
}

// ---------------------------------------------------------------------------
// W transposes (all three in one launch, z selects), output C-dim permuted
// ---------------------------------------------------------------------------
__global__ __launch_bounds__(256)
void transpose_w(const float* __restrict__ Wq, const float* __restrict__ Wk,
                 const float* __restrict__ Wv)
{
    __shared__ float tile[32][33];
    const int z = blockIdx.z;
    const float* I = (z == 0) ? Wq : (z == 1) ? Wk : Wv;
    float* O = g_WT[z];
    const int r0 = blockIdx.y * 32, c0 = blockIdx.x * 32;   // r: C dim, c: H dim
    const int tx = threadIdx.x & 31, ty = threadIdx.x >> 5;
    #pragma unroll
    for (int i = 0; i < 32; i += 8)
        tile[ty + i][tx] = I[(size_t)(r0 + ty + i) * H_ + c0 + tx];
    __syncthreads();
    const int fp = kperm(r0 + tx);
    #pragma unroll
    for (int i = 0; i < 32; i += 8)
        O[(size_t)(c0 + ty + i) * C_ + fp] = round_tf32(tile[tx][ty + i]);
}

// ---------------------------------------------------------------------------
// V transpose per batch: [T,H] -> [H,T], T-dim (GEMM K) permuted
// ---------------------------------------------------------------------------
__global__ __launch_bounds__(256)
void transpose_v()
{
    __shared__ float tile[32][33];
    const int z = blockIdx.z;
    const float* I = g_V  + (size_t)z * T_ * H_;
    float*       O = g_VT + (size_t)z * H_ * T_;
    const int r0 = blockIdx.y * 32, c0 = blockIdx.x * 32;   // r: T dim, c: H dim
    const int tx = threadIdx.x & 31, ty = threadIdx.x >> 5;
    #pragma unroll
    for (int i = 0; i < 32; i += 8)
        tile[ty + i][tx] = I[(size_t)(r0 + ty + i) * H_ + c0 + tx];
    __syncthreads();
    const int fp = kperm(r0 + tx);
    #pragma unroll
    for (int i = 0; i < 32; i += 8)
        O[(size_t)(c0 + ty + i) * T_ + fp] = tile[tx][ty + i];
}

// ---------------------------------------------------------------------------
// 2-pass causal softmax: pass1 row max; pass2 exp+sum+permuted tf32 write
// (UNNORMALIZED — 1/sum stored in g_inv, applied in pv epilogue).
// ---------------------------------------------------------------------------
__global__ __launch_bounds__(256)
void softmax_causal()
{
    const int row = blockIdx.x;
    const int b   = row >> 11;
    const int q   = row & (T_ - 1);
    float* Sr = g_S + (size_t)b * T_ * T_ + (size_t)q * T_;
    const int L = q + 1;
    const int Lpad = (q & ~127) + 128;
    const int tid = threadIdx.x;

    __shared__ float red[8];

    float m = -INFINITY;
    for (int k = tid * 4; k < Lpad; k += 1024) {
        float4 v = *(const float4*)&Sr[k];
        if (k + 0 < L) m = fmaxf(m, v.x);
        if (k + 1 < L) m = fmaxf(m, v.y);
        if (k + 2 < L) m = fmaxf(m, v.z);
        if (k + 3 < L) m = fmaxf(m, v.w);
    }
    #pragma unroll
    for (int o = 16; o > 0; o >>= 1) m = fmaxf(m, __shfl_xor_sync(0xFFFFFFFFu, m, o));
    if ((tid & 31) == 0) red[tid >> 5] = m;
    __syncthreads();
    float m_all = red[0];
    #pragma unroll
    for (int i = 1; i < 8; i++) m_all = fmaxf(m_all, red[i]);
    __syncthreads();

    // pass 2: exp, sum, write tf32-rounded + pair-permuted (unnormalized)
    float ssum = 0.0f;
    for (int k = tid * 4; k < Lpad; k += 1024) {
        float4 v = *(const float4*)&Sr[k];
        float4 e;
        e.x = (k + 0 < L) ? __expf(v.x - m_all) : 0.0f;
        e.y = (k + 1 < L) ? __expf(v.y - m_all) : 0.0f;
        e.z = (k + 2 < L) ? __expf(v.z - m_all) : 0.0f;
        e.w = (k + 3 < L) ? __expf(v.w - m_all) : 0.0f;
        ssum += e.x + e.y + e.z + e.w;
        __syncwarp();
        const int base = k & ~7;
        const int k0   = k & 7;
        Sr[base + kperm(k0 + 0)] = round_tf32(e.x);
        Sr[base + kperm(k0 + 1)] = round_tf32(e.y);
        Sr[base + kperm(k0 + 2)] = round_tf32(e.z);
        Sr[base + kperm(k0 + 3)] = round_tf32(e.w);
    }
    #pragma unroll
    for (int o = 16; o > 0; o >>= 1) ssum += __shfl_xor_sync(0xFFFFFFFFu, ssum, o);
    if ((tid & 31) == 0) red[tid >> 5] = ssum;
    __syncthreads();
    if (tid == 0) {
        float s_all = 0.0f;
        #pragma unroll
        for (int i = 0; i < 8; i++) s_all += red[i];
        g_inv[row] = 1.0f / s_all;
    }
}

// ---------------------------------------------------------------------------
// Launch
// ---------------------------------------------------------------------------
extern "C" void kernel_launch(void* const* d_in, const int* in_sizes, int n_in,
                              void* d_out, int out_size)
{
    const float* x  = (const float*)d_in[0];
    const float* Wq = (const float*)d_in[1];
    const float* Wk = (const float*)d_in[2];
    const float* Wv = (const float*)d_in[3];
    float* out = (float*)d_out;

    float *wtp;
    cudaGetSymbolAddress((void**)&wtp, g_WT);

    cudaFuncSetAttribute(proj_mma, cudaFuncAttributeMaxDynamicSharedMemorySize, SMEM_TOTAL);
    cudaFuncSetAttribute(qk_mma,   cudaFuncAttributeMaxDynamicSharedMemorySize, SMEM_TOTAL);
    cudaFuncSetAttribute(pv_mma,   cudaFuncAttributeMaxDynamicSharedMemorySize, SMEM_TOTAL);

    cvt_x<<<(B_ * T_ * C_) / (256 * 4), 256>>>(x);

    dim3 gtw(H_ / 32, C_ / 32, 3);
    transpose_w<<<gtw, 256>>>(Wq, Wk, Wv);

    dim3 gproj(H_ / BN, (B_ * T_) / BM, 3);
    proj_mma<<<gproj, NTHR, SMEM_TOTAL>>>(
        wtp, wtp + (size_t)H_ * C_, wtp + 2 * (size_t)H_ * C_);

    dim3 gtv(H_ / 32, T_ / 32, B_);
    transpose_v<<<gtv, 256>>>();

    dim3 gqk(T_ / 128, T_ / 128, B_);
    qk_mma<<<gqk, NTHR, SMEM_TOTAL>>>();

    softmax_causal<<<B_ * T_, 256>>>();

    dim3 gpv(H_ / 128, T_ / 128, B_);
    pv_mma<<<gpv, NTHR, SMEM_TOTAL>>>(out);
}

// round 7
// speedup vs baseline: 4.3606x; 1.0128x over previous
#include <cuda_runtime.h>
#include <cstdint>
#include <math.h>

#define B_  8
#define T_  2048
#define C_  1024
#define H_  1024
#define SCALE_ (1.0f / 32.0f)

// GEMM tiling
#define BM 128
#define BN 128
#define BK 32
#define NTHR 128
#define A_ST_BYTES 16384
#define STAGE_BYTES 32768
#define NSTAGES 3
#define SMEM_TOTAL (STAGE_BYTES * NSTAGES)   // 98304 -> 2 CTAs/SM

__host__ __device__ __forceinline__ int kperm(int k) {
    return (k & ~7) | (((k & 3) << 1) | ((k & 7) >> 2));
}

// ---------------------------------------------------------------------------
// Scratch (device globals) — GEMM operands stored K-pair-permuted
// ---------------------------------------------------------------------------
__device__ float g_X  [(size_t)B_ * T_ * C_];
__device__ float g_Q  [(size_t)B_ * T_ * H_];
__device__ float g_K  [(size_t)B_ * T_ * H_];
__device__ float g_V  [(size_t)B_ * T_ * H_];
__device__ float g_VT [(size_t)B_ * H_ * T_];
__device__ float g_S  [(size_t)B_ * T_ * T_];   // exp'd, permuted, unnormalized
__device__ float g_WT [3][(size_t)H_ * C_];
__device__ float g_sum[(size_t)B_ * T_];        // softmax row sums (atomic)

// ---------------------------------------------------------------------------
// Helpers
// ---------------------------------------------------------------------------
__device__ __forceinline__ uint32_t f2tf32(float f) {
    uint32_t r;
    asm("cvt.rna.tf32.f32 %0, %1;" : "=r"(r) : "f"(f));
    return r;
}
__device__ __forceinline__ float round_tf32(float f) {
    return __uint_as_float(f2tf32(f));
}
__device__ __forceinline__ void mma_tf32(float c[4], const uint32_t a[4],
                                         const uint32_t b[2]) {
    asm volatile(
        "mma.sync.aligned.m16n8k8.row.col.f32.tf32.tf32.f32 "
        "{%0,%1,%2,%3}, {%4,%5,%6,%7}, {%8,%9}, {%0,%1,%2,%3};"
        : "+f"(c[0]), "+f"(c[1]), "+f"(c[2]), "+f"(c[3])
        : "r"(a[0]), "r"(a[1]), "r"(a[2]), "r"(a[3]), "r"(b[0]), "r"(b[1]));
}
__device__ __forceinline__ void cp16(uint32_t d, const void* s) {
    asm volatile("cp.async.cg.shared.global [%0], [%1], 16;" :: "r"(d), "l"(s));
}
__device__ __forceinline__ void cp_commit() { asm volatile("cp.async.commit_group;"); }
__device__ __forceinline__ void cp_wait1()  { asm volatile("cp.async.wait_group 1;"); }
__device__ __forceinline__ void cp_wait0()  { asm volatile("cp.async.wait_group 0;"); }

// ---------------------------------------------------------------------------
// GEMM core. MODE 0: plain (scale, optional tf32-round, optional perm write)
//            MODE 1: qk fused softmax (exp + causal mask + row-sum atomics,
//                    permuted tf32 write)
//            MODE 2: pv deferred normalization (divide by rowsum[row])
// Single __syncthreads per k-tile; 3-stage cp.async; frag double buffering.
// ---------------------------------------------------------------------------
template<int MODE>
__device__ __forceinline__ void gemm_core(const float* __restrict__ Ag, int lda,
                                          const float* __restrict__ Bg, int ldb,
                                          float* __restrict__ Cg, int ldc,
                                          int nt, float scale,
                                          const float* __restrict__ rowsum,
                                          float* __restrict__ sumatomic,
                                          int gq0, int gn0,
                                          bool round_out, bool permute_out)
{
    extern __shared__ char dynsmem[];
    const int tid  = threadIdx.x;
    const int lane = tid & 31;
    const int wid  = tid >> 5;
    const int wm   = wid & 1;
    const int wn   = wid >> 1;
    const int g    = lane >> 2;
    const int t    = lane & 3;

    const uint32_t sb = (uint32_t)__cvta_generic_to_shared(dynsmem);
    const int r0 = tid >> 3;
    const int c4 = (tid & 7) << 2;

    auto issue = [&](int s, int buf) {
        const float* Abase = Ag + (size_t)s * BK;
        const float* Bbase = Bg + (size_t)s * BK;
        const uint32_t ab = sb + buf * STAGE_BYTES;
        const uint32_t bb = ab + A_ST_BYTES;
        #pragma unroll
        for (int i = 0; i < 8; i++) {
            const int r  = r0 + 16 * i;
            const int sc = c4 ^ ((r & 3) << 3);
            cp16(ab + r * 128 + sc * 4, Abase + (size_t)r * lda + c4);
            cp16(bb + r * 128 + sc * 4, Bbase + (size_t)r * ldb + c4);
        }
        cp_commit();
    };

    float acc[4][8][4];
    #pragma unroll
    for (int i = 0; i < 4; i++)
        #pragma unroll
        for (int j = 0; j < 8; j++)
            #pragma unroll
            for (int r = 0; r < 4; r++) acc[i][j][r] = 0.0f;

    issue(0, 0);
    issue(1, 1);

    const int mwb = wm * 64;
    const int nwb = wn * 64;
    const int swz = (g & 3) << 3;

    uint32_t ar[2][4][4], br[2][8][2];

    cp_wait1();
    __syncthreads();   // buffer 0 ready

    for (int s = 0; s < nt; s++) {
        if (s + 2 < nt) issue(s + 2, (s + 2) % NSTAGES);

        const uint32_t* As = (const uint32_t*)(dynsmem + (s % NSTAGES) * STAGE_BYTES);
        const uint32_t* Bs = (const uint32_t*)(dynsmem + (s % NSTAGES) * STAGE_BYTES + A_ST_BYTES);

        auto ldfrag = [&](int kk8, int pb) {
            const int cw = (kk8 * 8 + 2 * t) ^ swz;
            #pragma unroll
            for (int mf = 0; mf < 4; mf++) {
                const int rA = mwb + mf * 16 + g;
                uint2 v0 = *(const uint2*)&As[rA * 32 + cw];
                uint2 v1 = *(const uint2*)&As[(rA + 8) * 32 + cw];
                ar[pb][mf][0] = v0.x; ar[pb][mf][2] = v0.y;
                ar[pb][mf][1] = v1.x; ar[pb][mf][3] = v1.y;
            }
            #pragma unroll
            for (int nf = 0; nf < 8; nf++) {
                const int rB = nwb + nf * 8 + g;
                uint2 v = *(const uint2*)&Bs[rB * 32 + cw];
                br[pb][nf][0] = v.x; br[pb][nf][1] = v.y;
            }
        };

        ldfrag(0, 0);
        #pragma unroll
        for (int kk8 = 0; kk8 < 4; kk8++) {
            if (kk8 < 3) ldfrag(kk8 + 1, (kk8 + 1) & 1);
            const int pb = kk8 & 1;
            #pragma unroll
            for (int mf = 0; mf < 4; mf++)
                #pragma unroll
                for (int nf = 0; nf < 8; nf++)
                    mma_tf32(acc[mf][nf], ar[pb][mf], br[pb][nf]);
        }

        if (s + 1 < nt) {
            cp_wait1();
            __syncthreads();   // buffer s+1 ready; all compute(s) done
        }
    }

    // ---- Epilogue ----
    #pragma unroll
    for (int mf = 0; mf < 4; mf++) {
        const int row = mwb + mf * 16 + g;

        if (MODE == 1) {
            // qk: exp + causal mask + permuted tf32 write + row-sum atomics
            const int gq = gq0 + row;
            float rs0 = 0.0f, rs1 = 0.0f;
            #pragma unroll
            for (int nf = 0; nf < 8; nf++) {
                const int col = nwb + nf * 8 + 2 * t;
                const int gk  = gn0 + col;
                float e0 = (gq     >= gk    ) ? __expf(acc[mf][nf][0] * scale) : 0.0f;
                float e1 = (gq     >= gk + 1) ? __expf(acc[mf][nf][1] * scale) : 0.0f;
                float e2 = (gq + 8 >= gk    ) ? __expf(acc[mf][nf][2] * scale) : 0.0f;
                float e3 = (gq + 8 >= gk + 1) ? __expf(acc[mf][nf][3] * scale) : 0.0f;
                rs0 += e0 + e1;
                rs1 += e2 + e3;
                const int p0 = kperm(col), p1 = kperm(col + 1);
                Cg[(size_t)row * ldc + p0]       = round_tf32(e0);
                Cg[(size_t)row * ldc + p1]       = round_tf32(e1);
                Cg[(size_t)(row + 8) * ldc + p0] = round_tf32(e2);
                Cg[(size_t)(row + 8) * ldc + p1] = round_tf32(e3);
            }
            // reduce over t (lanes xor 1, 2)
            rs0 += __shfl_xor_sync(0xFFFFFFFFu, rs0, 1);
            rs0 += __shfl_xor_sync(0xFFFFFFFFu, rs0, 2);
            rs1 += __shfl_xor_sync(0xFFFFFFFFu, rs1, 1);
            rs1 += __shfl_xor_sync(0xFFFFFFFFu, rs1, 2);
            if (t == 0) {
                atomicAdd(&sumatomic[row], rs0);
                atomicAdd(&sumatomic[row + 8], rs1);
            }
        } else {
            float s0 = scale, s1 = scale;
            if (MODE == 2) {
                s0 = 1.0f / rowsum[row];
                s1 = 1.0f / rowsum[row + 8];
            }
            #pragma unroll
            for (int nf = 0; nf < 8; nf++) {
                const int col = nwb + nf * 8 + 2 * t;
                float v0 = acc[mf][nf][0] * s0, v1 = acc[mf][nf][1] * s0;
                float v2 = acc[mf][nf][2] * s1, v3 = acc[mf][nf][3] * s1;
                if (round_out) {
                    v0 = round_tf32(v0); v1 = round_tf32(v1);
                    v2 = round_tf32(v2); v3 = round_tf32(v3);
                }
                if (permute_out) {
                    const int p0 = kperm(col), p1 = kperm(col + 1);
                    Cg[(size_t)row * ldc + p0]       = v0;
                    Cg[(size_t)row * ldc + p1]       = v1;
                    Cg[(size_t)(row + 8) * ldc + p0] = v2;
                    Cg[(size_t)(row + 8) * ldc + p1] = v3;
                } else {
                    *(float2*)&Cg[(size_t)row * ldc + col]       = make_float2(v0, v1);
                    *(float2*)&Cg[(size_t)(row + 8) * ldc + col] = make_float2(v2, v3);
                }
            }
        }
    }
}

// ---------------------------------------------------------------------------
// GEMM wrappers
// ---------------------------------------------------------------------------
__global__ __launch_bounds__(NTHR, 2)
void proj_mma(const float* __restrict__ W0, const float* __restrict__ W1,
              const float* __restrict__ W2)
{
    const int z = blockIdx.z;
    const float* WT = (z == 0) ? W0 : (z == 1) ? W1 : W2;
    float* out = (z == 0) ? g_Q : (z == 1) ? g_K : g_V;
    const size_t m0 = (size_t)blockIdx.y * BM;
    const size_t n0 = (size_t)blockIdx.x * BN;
    gemm_core<0>(g_X + m0 * C_, C_, WT + n0 * C_, C_,
                 out + m0 * H_ + n0, H_, C_ / BK, 1.0f,
                 nullptr, nullptr, 0, 0, true, z < 2);
}

__global__ __launch_bounds__(NTHR, 2)
void qk_mma()
{
    const int kb = blockIdx.x, qb = blockIdx.y;
    if (kb > qb) return;
    const int b = blockIdx.z;
    const size_t q0 = (size_t)qb * 128, n0 = (size_t)kb * 128;
    gemm_core<1>(g_Q + (size_t)b * T_ * H_ + q0 * H_, H_,
                 g_K + (size_t)b * T_ * H_ + n0 * H_, H_,
                 g_S + (size_t)b * T_ * T_ + q0 * T_ + n0, T_,
                 H_ / BK, SCALE_,
                 nullptr, g_sum + (size_t)b * T_ + q0, (int)q0, (int)n0,
                 false, false);
}

__global__ __launch_bounds__(NTHR, 2)
void pv_mma(float* __restrict__ out)
{
    const int nb = blockIdx.x, qb = blockIdx.y, b = blockIdx.z;
    const size_t q0 = (size_t)qb * 128, n0 = (size_t)nb * 128;
    gemm_core<2>(g_S  + (size_t)b * T_ * T_ + q0 * T_, T_,
                 g_VT + (size_t)b * H_ * T_ + n0 * T_, T_,
                 out + (size_t)b * T_ * H_ + q0 * H_ + n0, H_,
                 (qb + 1) * 4, 1.0f,
                 g_sum + (size_t)b * T_ + q0, nullptr, 0, 0,
                 false, false);
}

// ---------------------------------------------------------------------------
// x -> tf32-rounded, K-pair-permuted copy
// ---------------------------------------------------------------------------
__global__ __launch_bounds__(256)
void cvt_x(const float* __restrict__ in)
{
    const size_t i = ((size_t)blockIdx.x * 256 + threadIdx.x) * 4;
    float4 v = *(const float4*)(in + i);
    const size_t base = i & ~(size_t)7;
    const int k0 = (int)(i & 7);
    g_X[base + kperm(k0 + 0)] = round_tf32(v.x);
    g_X[base + kperm(k0 + 1)] = round_tf32(v.y);
    g_X[base + kperm(k0 + 2)] = round_tf32(v.z);
    g_X[base + kperm(k0 + 3)] = round_tf32(v.w);
}

// ---------------------------------------------------------------------------
// Zero softmax row-sum accumulators
// ---------------------------------------------------------------------------
__global__ __launch_bounds__(256)
void zero_sums()
{
    g_sum[(size_t)blockIdx.x * 256 + threadIdx.x] = 0.0f;
}

// ---------------------------------------------------------------------------
// W transposes (3 in one launch), output C-dim permuted
// ---------------------------------------------------------------------------
__global__ __launch_bounds__(256)
void transpose_w(const float* __restrict__ Wq, const float* __restrict__ Wk,
                 const float* __restrict__ Wv)
{
    __shared__ float tile[32][33];
    const int z = blockIdx.z;
    const float* I = (z == 0) ? Wq : (z == 1) ? Wk : Wv;
    float* O = g_WT[z];
    const int r0 = blockIdx.y * 32, c0 = blockIdx.x * 32;
    const int tx = threadIdx.x & 31, ty = threadIdx.x >> 5;
    #pragma unroll
    for (int i = 0; i < 32; i += 8)
        tile[ty + i][tx] = I[(size_t)(r0 + ty + i) * H_ + c0 + tx];
    __syncthreads();
    const int fp = kperm(r0 + tx);
    #pragma unroll
    for (int i = 0; i < 32; i += 8)
        O[(size_t)(c0 + ty + i) * C_ + fp] = round_tf32(tile[tx][ty + i]);
}

// ---------------------------------------------------------------------------
// V transpose per batch: [T,H] -> [H,T], T-dim permuted
// ---------------------------------------------------------------------------
__global__ __launch_bounds__(256)
void transpose_v()
{
    __shared__ float tile[32][33];
    const int z = blockIdx.z;
    const float* I = g_V  + (size_t)z * T_ * H_;
    float*       O = g_VT + (size_t)z * H_ * T_;
    const int r0 = blockIdx.y * 32, c0 = blockIdx.x * 32;
    const int tx = threadIdx.x & 31, ty = threadIdx.x >> 5;
    #pragma unroll
    for (int i = 0; i < 32; i += 8)
        tile[ty + i][tx] = I[(size_t)(r0 + ty + i) * H_ + c0 + tx];
    __syncthreads();
    const int fp = kperm(r0 + tx);
    #pragma unroll
    for (int i = 0; i < 32; i += 8)
        O[(size_t)(c0 + ty + i) * T_ + fp] = tile[tx][ty + i];
}

// ---------------------------------------------------------------------------
// Launch
// ---------------------------------------------------------------------------
extern "C" void kernel_launch(void* const* d_in, const int* in_sizes, int n_in,
                              void* d_out, int out_size)
{
    const float* x  = (const float*)d_in[0];
    const float* Wq = (const float*)d_in[1];
    const float* Wk = (const float*)d_in[2];
    const float* Wv = (const float*)d_in[3];
    float* out = (float*)d_out;

    float* wtp;
    cudaGetSymbolAddress((void**)&wtp, g_WT);

    cudaFuncSetAttribute(proj_mma, cudaFuncAttributeMaxDynamicSharedMemorySize, SMEM_TOTAL);
    cudaFuncSetAttribute(qk_mma,   cudaFuncAttributeMaxDynamicSharedMemorySize, SMEM_TOTAL);
    cudaFuncSetAttribute(pv_mma,   cudaFuncAttributeMaxDynamicSharedMemorySize, SMEM_TOTAL);

    cvt_x<<<(B_ * T_ * C_) / (256 * 4), 256>>>(x);
    zero_sums<<<(B_ * T_) / 256, 256>>>();

    dim3 gtw(H_ / 32, C_ / 32, 3);
    transpose_w<<<gtw, 256>>>(Wq, Wk, Wv);

    dim3 gproj(H_ / BN, (B_ * T_) / BM, 3);
    proj_mma<<<gproj, NTHR, SMEM_TOTAL>>>(
        wtp, wtp + (size_t)H_ * C_, wtp + 2 * (size_t)H_ * C_);

    dim3 gtv(H_ / 32, T_ / 32, B_);
    transpose_v<<<gtv, 256>>>();

    // qk with fused exp + causal mask + row-sum atomics
    dim3 gqk(T_ / 128, T_ / 128, B_);
    qk_mma<<<gqk, NTHR, SMEM_TOTAL>>>();

    // pv with deferred normalization
    dim3 gpv(H_ / 128, T_ / 128, B_);
    pv_mma<<<gpv, NTHR, SMEM_TOTAL>>>(out);
}